// round 7
// baseline (speedup 1.0000x reference)
#include <cuda_runtime.h>
#include <math.h>

#define Bn 512
#define Ln 64
#define En 256
#define Hn 256
#define CD 64
#define HCn 320     // H + CDIM
#define KX 512      // E + H
#define G4 1024     // 4*H
#define NEGV -1000000000.0f
#define NBLK 256    // every phase = whole multiple of jobs per block

// ---------------- scratch (static device globals; allocation-free) ----------
__device__ float g_eg[Bn*Ln*Hn];     // e_g  [b][l][h]
__device__ float g_ep[Bn*Ln*Hn];     // e_p  [b][l][h]
__device__ float g_xh[Bn*KX];        // [x | h] LSTM input
__device__ float g_hc[Bn*HCn];       // [h | courier]
__device__ float g_c[Bn*Hn];
__device__ float g_gl[Bn*Hn];
__device__ float g_qg[Bn*Hn];
__device__ float g_gl2[Bn*Hn];
__device__ float g_qp[Bn*Hn];
__device__ float g_Wcat[G4*KX];      // [W_ih | W_hh]
__device__ float g_bcat[G4];         // b_ih + b_hh
__device__ unsigned char g_mask[Bn*Ln];
__device__ unsigned int g_sync;      // grid barrier counter (reset each launch)

__device__ __forceinline__ float sigf(float x) { return 1.0f/(1.0f+expf(-x)); }

// ---------------- IVALL-free grid barrier (release/acquire, no threadfence) -
__device__ __forceinline__ void gbar(unsigned int &cnt) {
    __syncthreads();
    cnt += gridDim.x;
    if (threadIdx.x == 0) {
        unsigned int* sp;
        asm volatile("mov.u64 %0, g_sync;" : "=l"(sp));
        asm volatile("red.release.gpu.global.add.u32 [%0], 1;" :: "l"(sp) : "memory");
        unsigned int v;
        do {
            asm volatile("ld.acquire.gpu.global.u32 %0, [%1];" : "=r"(v) : "l"(sp) : "memory");
        } while (v < cnt);
    }
    __syncthreads();
}

// ---------------- P1: fused gates GEMM + LSTM epilogue ----------------------
// gates[b][n] = sum_k xh[b][k]*Wcat[n][k] + bcat[n]; then LSTM pointwise.
// Tile: 16 batch rows x 32 j-cols x 4 gate groups. 256 jobs (32 m x 8 j tiles).
__device__ void gates_lstm(char* sm)
{
    float (*sA)[16][16]  = (float (*)[16][16])sm;             // 2 KB
    float (*sW)[16][128] = (float (*)[16][128])(sm + 2048);   // 16 KB
    const int tid = threadIdx.x;
    const int job = blockIdx.x;
    const int m0 = (job & 31) << 4;     // 32 m-tiles of 16
    const int j0 = (job >> 5) << 5;     // 8 j-tiles of 32
    const int tm = tid >> 5;            // 0..7 -> rows {tm, tm+8}
    const int tj = tid & 31;            // j within tile
    const bool aAct = tid < 64;
    const int ar = tid >> 2, ak = (tid & 3) << 2;
    const int wr = tid >> 1, wk = (tid & 1) << 3;
    const int wg = wr >> 5, wj = wr & 31;

    const float* Ap = g_xh + (size_t)(m0 + ar) * KX + ak;
    const float* Wp = g_Wcat + (size_t)(wg * 256 + j0 + wj) * KX + wk;

    float4 ra, rw0, rw1;
    if (aAct) ra = __ldcg((const float4*)Ap);
    rw0 = *(const float4*)(Wp);
    rw1 = *(const float4*)(Wp + 4);
    float acc[2][4] = {};
    __syncthreads();                    // smem reuse across phases
    int buf = 0;
    for (int k0 = 0; k0 < KX; k0 += 16) {
        if (aAct) {
            sA[buf][ak+0][ar]=ra.x; sA[buf][ak+1][ar]=ra.y;
            sA[buf][ak+2][ar]=ra.z; sA[buf][ak+3][ar]=ra.w;
        }
        sW[buf][wk+0][wr]=rw0.x; sW[buf][wk+1][wr]=rw0.y;
        sW[buf][wk+2][wr]=rw0.z; sW[buf][wk+3][wr]=rw0.w;
        sW[buf][wk+4][wr]=rw1.x; sW[buf][wk+5][wr]=rw1.y;
        sW[buf][wk+6][wr]=rw1.z; sW[buf][wk+7][wr]=rw1.w;
        __syncthreads();
        if (k0 + 16 < KX) {
            if (aAct) ra = __ldcg((const float4*)(Ap + k0 + 16));
            rw0 = *(const float4*)(Wp + k0 + 16);
            rw1 = *(const float4*)(Wp + k0 + 20);
        }
        #pragma unroll
        for (int kk = 0; kk < 16; kk++) {
            const float a0 = sA[buf][kk][tm];
            const float a1 = sA[buf][kk][tm + 8];
            #pragma unroll
            for (int g = 0; g < 4; g++) {
                const float w = sW[buf][kk][g*32 + tj];
                acc[0][g] = fmaf(a0, w, acc[0][g]);
                acc[1][g] = fmaf(a1, w, acc[1][g]);
            }
        }
        buf ^= 1;
    }
    const int j = j0 + tj;
    const float bi = g_bcat[j], bf = g_bcat[j+256];
    const float bg = g_bcat[j+512], bo = g_bcat[j+768];
    #pragma unroll
    for (int r = 0; r < 2; r++) {
        const int b = m0 + tm + r*8;
        float iv = sigf(acc[r][0] + bi);
        float fv = sigf(acc[r][1] + bf);
        float gv = tanhf(acc[r][2] + bg);
        float ov = sigf(acc[r][3] + bo);
        float cold = g_c[b*Hn + j];          // block-private across steps
        float c = fv * cold + iv * gv;
        float h = ov * tanhf(c);
        g_c[b*Hn + j]       = c;
        g_xh[b*KX + En + j] = h;
        g_hc[b*HCn + j]     = h;
    }
}

// ---------------- small GEMM: 8x64 tiles, 256 jobs (M=512, N=256) -----------
template<int K>
__device__ void gemm_small(const float* __restrict__ A, const float* __restrict__ W,
                           const float* __restrict__ bias, float* __restrict__ C,
                           char* sm)
{
    float (*sA)[16][8]  = (float (*)[16][8])sm;             // 1 KB
    float (*sW)[16][64] = (float (*)[16][64])(sm + 1024);   // 8 KB
    const int tid = threadIdx.x;
    const int job = blockIdx.x;
    const int m0 = (job & 63) << 3;         // 64 m-tiles
    const int n0 = (job >> 6) << 6;         // 4 n-tiles
    const int tr = tid >> 5;                // 0..7 output row
    const int tc = tid & 31;                // cols 2tc, 2tc+1
    const bool aAct = tid < 32;
    const int am = tid >> 2;                // 0..7
    const int ak = (tid & 3) << 2;
    const int wn = tid >> 2;                // 0..63
    const int wk = (tid & 3) << 2;

    const float* Arow = A + (size_t)(m0 + am) * K + ak;
    const float* Wrow = W + (size_t)(n0 + wn) * K + wk;
    float4 ra, rw;
    if (aAct) ra = __ldcg((const float4*)Arow);   // cross-block data: L2
    rw = *(const float4*)Wrow;
    float acc0 = 0.f, acc1 = 0.f;
    __syncthreads();
    int buf = 0;
    for (int k0 = 0; k0 < K; k0 += 16) {
        if (aAct) {
            sA[buf][ak+0][am]=ra.x; sA[buf][ak+1][am]=ra.y;
            sA[buf][ak+2][am]=ra.z; sA[buf][ak+3][am]=ra.w;
        }
        sW[buf][wk+0][wn]=rw.x; sW[buf][wk+1][wn]=rw.y;
        sW[buf][wk+2][wn]=rw.z; sW[buf][wk+3][wn]=rw.w;
        __syncthreads();
        if (k0 + 16 < K) {
            if (aAct) ra = __ldcg((const float4*)(Arow + k0 + 16));
            rw = *(const float4*)(Wrow + k0 + 16);
        }
        #pragma unroll
        for (int kk = 0; kk < 16; kk++) {
            const float a = sA[buf][kk][tr];
            const float2 w = *(const float2*)&sW[buf][kk][tc<<1];
            acc0 = fmaf(a, w.x, acc0);
            acc1 = fmaf(a, w.y, acc1);
        }
        buf ^= 1;
    }
    const int nc = n0 + (tc << 1);
    *(float2*)(C + (size_t)(m0+tr)*Hn + nc) =
        make_float2(acc0 + bias[nc], acc1 + bias[nc+1]);
}

// ---------------- one-time e_g/e_p GEMM (unchanged) -------------------------
template<int REMAP>
__global__ __launch_bounds__(256) void gemm_bias(
    const float* __restrict__ A, const float* __restrict__ W,
    const float* __restrict__ bias, float* __restrict__ C,
    int M, int N, int K)
{
    __shared__ float As[16][64];
    __shared__ float Ws[16][64];
    const int m0 = blockIdx.y * 64, n0 = blockIdx.x * 64;
    const int tid = threadIdx.x;
    const int lr = tid >> 2;
    const int lc = (tid & 3) * 4;
    const int ty = tid >> 4, tx = tid & 15;

    float acc[4][4] = {};
    int mrow = m0 + lr;
    int arow = REMAP ? ((mrow & 63) * Bn + (mrow >> 6)) : mrow;
    const float* Ap = A + (size_t)arow * K + lc;
    const float* Wp = W + (size_t)(n0 + lr) * K + lc;

    for (int k0 = 0; k0 < K; k0 += 16) {
        float4 av = *(const float4*)(Ap + k0);
        float4 wv = *(const float4*)(Wp + k0);
        As[lc+0][lr]=av.x; As[lc+1][lr]=av.y; As[lc+2][lr]=av.z; As[lc+3][lr]=av.w;
        Ws[lc+0][lr]=wv.x; Ws[lc+1][lr]=wv.y; Ws[lc+2][lr]=wv.z; Ws[lc+3][lr]=wv.w;
        __syncthreads();
        #pragma unroll
        for (int kk = 0; kk < 16; kk++) {
            float4 a = *(const float4*)&As[kk][ty*4];
            float4 w = *(const float4*)&Ws[kk][tx*4];
            float ar[4] = {a.x,a.y,a.z,a.w};
            float wr[4] = {w.x,w.y,w.z,w.w};
            #pragma unroll
            for (int i = 0; i < 4; i++)
                #pragma unroll
                for (int j = 0; j < 4; j++)
                    acc[i][j] += ar[i]*wr[j];
        }
        __syncthreads();
    }
    #pragma unroll
    for (int i = 0; i < 4; i++) {
        int m = m0 + ty*4 + i;
        float* Crow = C + (size_t)m*N + n0 + tx*4;
        #pragma unroll
        for (int j = 0; j < 4; j++)
            Crow[j] = acc[i][j] + bias[n0 + tx*4 + j];
    }
}

// ---------------- one-time setup ----------------
__global__ void setup_kernel(
    const float* __restrict__ dec, const float* __restrict__ h0,
    const float* __restrict__ c0, const float* __restrict__ courier,
    const unsigned char* __restrict__ im,
    const float* __restrict__ W_ih, const float* __restrict__ W_hh,
    const float* __restrict__ b_ih, const float* __restrict__ b_hh)
{
    int i = blockIdx.x * blockDim.x + threadIdx.x;
    if (i == 0) g_sync = 0;                       // reset grid barrier each launch
    if (i < G4*KX) {
        int n = i / KX, k = i % KX;
        g_Wcat[i] = (k < En) ? W_ih[n*En + k] : W_hh[n*Hn + (k - En)];
    }
    if (i < G4)    g_bcat[i] = b_ih[i] + b_hh[i];
    if (i < Bn*KX) {
        int b = i / KX, j = i % KX;
        g_xh[i] = (j < En) ? dec[b*En + j] : h0[b*Hn + (j - En)];
    }
    if (i < Bn*Hn) g_c[i] = c0[i];
    if (i < Bn*CD) {
        int b = i / CD, j = i % CD;
        g_hc[b*HCn + Hn + j] = courier[i];
    }
    if (i < Bn*Ln) g_mask[i] = im[i];
}

// ---------------- the persistent decoder kernel -----------------------------
__global__ __launch_bounds__(256, 3) void persist_kernel(
    const float* __restrict__ emb,
    const float* __restrict__ Wm,   const float* __restrict__ bm,
    const float* __restrict__ Wq_g, const float* __restrict__ bq_g,
    const float* __restrict__ Wq_p, const float* __restrict__ bq_p,
    const float* __restrict__ v_g,  const float* __restrict__ v_p,
    float* __restrict__ out)
{
    extern __shared__ char smc[];                // 18.5 KB GEMM buffers
    __shared__ float wv[64];
    __shared__ float s_m, s_ls;
    __shared__ int   s_sel;

    const int t = threadIdx.x;
    const int warp = t >> 5, lane = t & 31;
    unsigned int barcnt = 0;

    for (int step = 0; step < Ln; step++) {
        // ---- P1: gates GEMM + LSTM pointwise (fused) ----
        gates_lstm(smc);
        gbar(barcnt);

        // ---- P2: gl = [h|courier] @ Wm^T + bm  (K=320) ----
        gemm_small<HCn>(g_hc, Wm, bm, g_gl, smc);
        gbar(barcnt);

        // ---- P3: qg = gl @ Wq_g^T + bq_g ----
        gemm_small<Hn>(g_gl, Wq_g, bq_g, g_qg, smc);
        gbar(barcnt);

        // ---- P4: attention g (scores + softmax + weighted sum) ----
        for (int b = blockIdx.x; b < Bn; b += gridDim.x) {
            __syncthreads();                      // protect wv reuse
            const float* E = g_eg + (size_t)b * Ln * Hn;
            float qr[8], vr[8];
            #pragma unroll
            for (int j = 0; j < 8; j++) {
                qr[j] = __ldcg(g_qg + b*Hn + lane + 32*j);  // cross-block
                vr[j] = v_g[lane + 32*j];
            }
            #pragma unroll
            for (int l0 = 0; l0 < 64; l0 += 8) {
                int l = l0 + warp;
                const float* row = E + l * 256;
                float acc = 0.f;
                #pragma unroll
                for (int j = 0; j < 8; j++)
                    acc += vr[j] * tanhf(qr[j] + row[lane + 32*j]);
                #pragma unroll
                for (int o = 16; o; o >>= 1) acc += __shfl_xor_sync(0xffffffffu, acc, o);
                if (lane == 0) wv[l] = g_mask[b*Ln + l] ? NEGV : acc;
            }
            __syncthreads();

            if (warp == 0) {
                float a = wv[lane], c = wv[lane + 32];
                float m = fmaxf(a, c);
                #pragma unroll
                for (int o = 16; o; o >>= 1) m = fmaxf(m, __shfl_xor_sync(0xffffffffu, m, o));
                float ea = expf(a - m), ec = expf(c - m);
                float s = ea + ec;
                #pragma unroll
                for (int o = 16; o; o >>= 1) s += __shfl_xor_sync(0xffffffffu, s, o);
                wv[lane]      = ea / s;
                wv[lane + 32] = ec / s;
            }
            __syncthreads();

            float acc = 0.f;
            #pragma unroll 8
            for (int l = 0; l < 64; l++) acc += E[l*256 + t] * wv[l];
            g_gl2[b*Hn + t] = acc;
        }
        gbar(barcnt);

        // ---- P5: qp = gl2 @ Wq_p^T + bq_p ----
        gemm_small<Hn>(g_gl2, Wq_p, bq_p, g_qp, smc);
        gbar(barcnt);

        // ---- P6: attention p (log-softmax + argmax + mask + gather) ----
        for (int b = blockIdx.x; b < Bn; b += gridDim.x) {
            __syncthreads();                      // protect wv reuse
            const float* E = g_ep + (size_t)b * Ln * Hn;
            float qr[8], vr[8];
            #pragma unroll
            for (int j = 0; j < 8; j++) {
                qr[j] = __ldcg(g_qp + b*Hn + lane + 32*j);  // cross-block
                vr[j] = v_p[lane + 32*j];
            }
            #pragma unroll
            for (int l0 = 0; l0 < 64; l0 += 8) {
                int l = l0 + warp;
                const float* row = E + l * 256;
                float acc = 0.f;
                #pragma unroll
                for (int j = 0; j < 8; j++)
                    acc += vr[j] * tanhf(qr[j] + row[lane + 32*j]);
                #pragma unroll
                for (int o = 16; o; o >>= 1) acc += __shfl_xor_sync(0xffffffffu, acc, o);
                if (lane == 0) wv[l] = g_mask[b*Ln + l] ? NEGV : (10.0f * tanhf(acc));
            }
            __syncthreads();

            if (warp == 0) {
                float a = wv[lane], c = wv[lane + 32];
                float m = fmaxf(a, c);
                #pragma unroll
                for (int o = 16; o; o >>= 1) m = fmaxf(m, __shfl_xor_sync(0xffffffffu, m, o));
                float s = expf(a - m) + expf(c - m);
                #pragma unroll
                for (int o = 16; o; o >>= 1) s += __shfl_xor_sync(0xffffffffu, s, o);
                float bv = a; int bi = lane;
                if (c > bv) { bv = c; bi = lane + 32; }
                #pragma unroll
                for (int o = 16; o; o >>= 1) {
                    float ov = __shfl_xor_sync(0xffffffffu, bv, o);
                    int   oi = __shfl_xor_sync(0xffffffffu, bi, o);
                    if (ov > bv || (ov == bv && oi < bi)) { bv = ov; bi = oi; }
                }
                if (lane == 0) {
                    s_m = m; s_ls = logf(s); s_sel = bi;
                    unsigned char* mk = g_mask + b*Ln;   // block-private
                    mk[bi] = 1;
                    int cnt = 0;
                    #pragma unroll
                    for (int l = 0; l < Ln; l++) cnt += mk[l];
                    if (cnt == Ln) mk[Ln - 1] = 0;
                    out[(size_t)(Bn*Ln*Ln) + (size_t)b*Ln + step] = (float)bi;
                }
            }
            __syncthreads();

            if (t < Ln)
                out[(size_t)b*Ln*Ln + (size_t)step*Ln + t] = wv[t] - s_m - s_ls;

            int sel = s_sel;
            g_xh[b*KX + t] = emb[((size_t)sel*Bn + b)*En + t];
        }
        gbar(barcnt);
    }
}

// ---------------- host ----------------
extern "C" void kernel_launch(void* const* d_in, const int* in_sizes, int n_in,
                              void* d_out, int out_size)
{
    const float* dec     = (const float*)d_in[0];
    const float* emb     = (const float*)d_in[1];
    const float* h0      = (const float*)d_in[2];
    const float* c0      = (const float*)d_in[3];
    const float* ctx     = (const float*)d_in[4];
    const float* courier = (const float*)d_in[5];
    const unsigned char* initm = (const unsigned char*)d_in[6];
    const float* W_ih = (const float*)d_in[7];
    const float* W_hh = (const float*)d_in[8];
    const float* b_ih = (const float*)d_in[9];
    const float* b_hh = (const float*)d_in[10];
    const float* Wm   = (const float*)d_in[11];
    const float* bm   = (const float*)d_in[12];
    const float* Wq_p = (const float*)d_in[13];
    const float* bq_p = (const float*)d_in[14];
    const float* Wr_p = (const float*)d_in[15];
    const float* br_p = (const float*)d_in[16];
    const float* v_p  = (const float*)d_in[17];
    const float* Wq_g = (const float*)d_in[18];
    const float* bq_g = (const float*)d_in[19];
    const float* Wr_g = (const float*)d_in[20];
    const float* br_g = (const float*)d_in[21];
    const float* v_g  = (const float*)d_in[22];
    float* out = (float*)d_out;

    cudaFuncSetAttribute(persist_kernel, cudaFuncAttributeMaxDynamicSharedMemorySize, 18432);

    float *eg, *ep;
    cudaGetSymbolAddress((void**)&eg, g_eg);
    cudaGetSymbolAddress((void**)&ep, g_ep);

    setup_kernel<<<1024, 512>>>(dec, h0, c0, courier, initm, W_ih, W_hh, b_ih, b_hh);

    // e_g / e_p = context @ Wr^T + br, stored [b][l][h]
    gemm_bias<1><<<dim3(Hn/64, (Bn*Ln)/64), 256>>>(ctx, Wr_g, br_g, eg, Bn*Ln, Hn, Hn);
    gemm_bias<1><<<dim3(Hn/64, (Bn*Ln)/64), 256>>>(ctx, Wr_p, br_p, ep, Bn*Ln, Hn, Hn);

    persist_kernel<<<NBLK, 256, 18432>>>(emb, Wm, bm, Wq_g, bq_g, Wq_p, bq_p,
                                         v_g, v_p, out);
}

// round 8
// speedup vs baseline: 1.0944x; 1.0944x over previous
#include <cuda_runtime.h>
#include <math.h>

#define Bn 512
#define Ln 64
#define En 256
#define Hn 256
#define CD 64
#define HCn 320     // H + CDIM
#define KX 512      // E + H
#define G4 1024     // 4*H
#define NEGV -1000000000.0f
#define NBLK 296    // 2 blocks/SM on 148 SMs

// ---------------- scratch (static device globals; allocation-free) ----------
__device__ float g_eg[Bn*Ln*Hn];     // e_g  [b][l][h]
__device__ float g_ep[Bn*Ln*Hn];     // e_p  [b][l][h]
__device__ float g_xh[Bn*KX];        // [x | h] LSTM input
__device__ float g_hc[Bn*HCn];       // [h | courier]
__device__ float g_gates[Bn*G4];
__device__ float g_c[Bn*Hn];
__device__ float g_gl[Bn*Hn];
__device__ float g_qg[Bn*Hn];
__device__ float g_gl2[Bn*Hn];
__device__ float g_qp[Bn*Hn];
__device__ float g_Wcat[G4*KX];      // [W_ih | W_hh]
__device__ float g_bcat[G4];         // b_ih + b_hh
__device__ unsigned char g_mask[Bn*Ln];
__device__ unsigned int g_sync;

typedef unsigned long long u64t;

__device__ __forceinline__ float sigf(float x) { return 1.0f/(1.0f+expf(-x)); }

// packed fp32x2 helpers (per-lane IEEE fp32 FMA, bit-identical to FFMA)
__device__ __forceinline__ u64t pk2(float lo, float hi) {
    u64t r; asm("mov.b64 %0, {%1, %2};" : "=l"(r) : "f"(lo), "f"(hi)); return r;
}
__device__ __forceinline__ void upk2(u64t v, float &lo, float &hi) {
    asm("mov.b64 {%0, %1}, %2;" : "=f"(lo), "=f"(hi) : "l"(v));
}
__device__ __forceinline__ u64t ffma2(u64t a, u64t b, u64t c) {
    u64t d; asm("fma.rn.f32x2 %0, %1, %2, %3;" : "=l"(d) : "l"(a), "l"(b), "l"(c));
    return d;
}

// [7/7] continued-fraction tanh: err ~1e-8 on |x|<=1; fallback beyond (never hit
// in practice: score args are ~N(0, 0.08^2)).
__device__ __forceinline__ float tanh_pade(float x) {
    float t = x * x;
    float num = fmaf(t, fmaf(t, (t + 378.0f), 17325.0f), 135135.0f) * x;
    float den = fmaf(t, fmaf(t, fmaf(t, 28.0f, 3150.0f), 62370.0f), 135135.0f);
    float r = __fdividef(num, den);
    if (t > 1.0f) r = tanhf(x);
    return r;
}

// ---------------- software grid barrier (R2 version) ------------------------
__device__ __forceinline__ void gbar(unsigned int &cnt) {
    __syncthreads();
    cnt += gridDim.x;
    if (threadIdx.x == 0) {
        __threadfence();
        atomicAdd(&g_sync, 1u);
        while (*(volatile unsigned int*)&g_sync < cnt) { }
        __threadfence();
    }
    __syncthreads();
}

// ---------------- gates GEMM: broadcast-W + f32x2, 32x64 tiles, 256 jobs ----
// C[m][n] = sum_k A[m][k]*W[n][k] + bias[n],  M=512 N=1024 K=512
__device__ void gemm_gates(const float* __restrict__ A, const float* __restrict__ W,
                           const float* __restrict__ bias, float* __restrict__ C,
                           float (*sA)[16][32], float (*sW)[16][64])
{
    const int tid = threadIdx.x;
    const int lane = tid & 31;
    const int w8 = (tid >> 5) << 3;        // warp col group: 0,8,...,56
    const bool aAct = tid < 128;
    const int ar = tid >> 2;               // A row (0..31 when aAct)
    const int ak = (tid & 3) << 2;
    const int wn = tid >> 2;               // W row 0..63
    const int wk = (tid & 3) << 2;

    for (int job = blockIdx.x; job < 256; job += gridDim.x) {
        const int m0 = (job & 15) << 5;    // 16 m-tiles of 32
        const int n0 = (job >> 4) << 6;    // 16 n-tiles of 64
        const float* Ap = A + (size_t)(m0 + ar) * KX + ak;
        const float* Wp = W + (size_t)(n0 + wn) * KX + wk;
        float4 ra, rw;
        if (aAct) ra = *(const float4*)Ap;
        rw = *(const float4*)Wp;
        u64t acc[4] = {0ull, 0ull, 0ull, 0ull};
        __syncthreads();                   // smem reuse across phases/jobs
        int buf = 0;
        for (int k0 = 0; k0 < KX; k0 += 16) {
            if (aAct) {
                (*sA)[0][0] = (*sA)[0][0];  // no-op guard removed by compiler
                sA[buf][ak+0][ar]=ra.x; sA[buf][ak+1][ar]=ra.y;
                sA[buf][ak+2][ar]=ra.z; sA[buf][ak+3][ar]=ra.w;
            }
            sW[buf][wk+0][wn]=rw.x; sW[buf][wk+1][wn]=rw.y;
            sW[buf][wk+2][wn]=rw.z; sW[buf][wk+3][wn]=rw.w;
            __syncthreads();
            if (k0 + 16 < KX) {
                if (aAct) ra = *(const float4*)(Ap + k0 + 16);
                rw = *(const float4*)(Wp + k0 + 16);
            }
            #pragma unroll
            for (int kk = 0; kk < 16; kk++) {
                const float a = sA[buf][kk][lane];
                const u64t ap = pk2(a, a);
                const ulonglong2 w0 = *(const ulonglong2*)&sW[buf][kk][w8];
                const ulonglong2 w1 = *(const ulonglong2*)&sW[buf][kk][w8 + 4];
                acc[0] = ffma2(ap, w0.x, acc[0]);
                acc[1] = ffma2(ap, w0.y, acc[1]);
                acc[2] = ffma2(ap, w1.x, acc[2]);
                acc[3] = ffma2(ap, w1.y, acc[3]);
            }
            buf ^= 1;
        }
        float r[8];
        upk2(acc[0], r[0], r[1]); upk2(acc[1], r[2], r[3]);
        upk2(acc[2], r[4], r[5]); upk2(acc[3], r[6], r[7]);
        float* Cr = C + (size_t)(m0 + lane) * G4 + n0 + w8;
        const float* bp = bias + n0 + w8;
        #pragma unroll
        for (int j = 0; j < 8; j++) Cr[j] = r[j] + bp[j];
    }
}

// ---------------- small GEMM (R2's gemm_phase, TM=16) -----------------------
template<int TM>
__device__ void gemm_phase(const float* __restrict__ A, const float* __restrict__ W,
                           const float* __restrict__ bias, float* __restrict__ C,
                           int M, int N, int K,
                           float (*sA)[16][32], float (*sW)[16][64])
{
    const int tid = threadIdx.x;
    const int tm = tid >> 4;
    const int tn = tid & 15;
    const int mt = M / TM, nt = N >> 6;
    const int njobs = mt * nt;
    const bool aAct = tid < TM * 4;
    const int am = tid >> 2;
    const int ak = (tid & 3) << 2;
    const int wn = tid >> 2;
    const int wk = (tid & 3) << 2;

    for (int job = blockIdx.x; job < njobs; job += gridDim.x) {
        const int m0 = (job % mt) * TM;
        const int n0 = (job / mt) << 6;
        const float* Arow = A + (size_t)(m0 + am) * K + ak;
        const float* Wrow = W + (size_t)(n0 + wn) * K + wk;
        float4 ra, rw;
        if (aAct) ra = *(const float4*)(Arow);
        rw = *(const float4*)(Wrow);
        float acc0[4] = {0,0,0,0};
        __syncthreads();
        int buf = 0;
        for (int k0 = 0; k0 < K; k0 += 16) {
            if (aAct) {
                sA[buf][ak+0][am] = ra.x; sA[buf][ak+1][am] = ra.y;
                sA[buf][ak+2][am] = ra.z; sA[buf][ak+3][am] = ra.w;
            }
            sW[buf][wk+0][wn] = rw.x; sW[buf][wk+1][wn] = rw.y;
            sW[buf][wk+2][wn] = rw.z; sW[buf][wk+3][wn] = rw.w;
            __syncthreads();
            if (k0 + 16 < K) {
                if (aAct) ra = *(const float4*)(Arow + k0 + 16);
                rw = *(const float4*)(Wrow + k0 + 16);
            }
            #pragma unroll
            for (int kk = 0; kk < 16; kk++) {
                const float4 w = *(const float4*)&sW[buf][kk][tn << 2];
                const float a0 = sA[buf][kk][tm];
                acc0[0] = fmaf(a0, w.x, acc0[0]);
                acc0[1] = fmaf(a0, w.y, acc0[1]);
                acc0[2] = fmaf(a0, w.z, acc0[2]);
                acc0[3] = fmaf(a0, w.w, acc0[3]);
            }
            buf ^= 1;
        }
        const int nc = n0 + (tn << 2);
        float b0 = bias[nc], b1 = bias[nc+1], b2 = bias[nc+2], b3 = bias[nc+3];
        float* Cr = C + (size_t)(m0 + tm) * N + nc;
        Cr[0] = acc0[0] + b0; Cr[1] = acc0[1] + b1;
        Cr[2] = acc0[2] + b2; Cr[3] = acc0[3] + b3;
    }
}

// ---------------- one-time e_g/e_p GEMM: broadcast-W + f32x2 ----------------
// A = context (L,B,H); output row m=(b*64+l) maps to A row (l*Bn + b).
// M=32768 rows, N=256, K=256. Grid 4096 blocks of 256.
__global__ __launch_bounds__(256) void gemm_e_bcast(
    const float* __restrict__ A, const float* __restrict__ W,
    const float* __restrict__ bias, float* __restrict__ C)
{
    __shared__ float sA[2][16][32];
    __shared__ float sW[2][16][64];
    __shared__ float stg[32 * 68];
    const int tid = threadIdx.x;
    const int lane = tid & 31;
    const int w8 = (tid >> 5) << 3;
    const bool aAct = tid < 128;
    const int ar = tid >> 2;
    const int ak = (tid & 3) << 2;
    const int wn = tid >> 2;
    const int wk = (tid & 3) << 2;

    const int job = blockIdx.x;
    const int m0 = (job & 1023) << 5;     // 1024 m-tiles of 32
    const int n0 = (job >> 10) << 6;      // 4 n-tiles of 64
    const int mrow = m0 + ar;
    const int arow = (mrow & 63) * Bn + (mrow >> 6);
    const float* Ap = A + (size_t)arow * Hn + ak;
    const float* Wp = W + (size_t)(n0 + wn) * Hn + wk;

    float4 ra, rw;
    if (aAct) ra = *(const float4*)Ap;
    rw = *(const float4*)Wp;
    u64t acc[4] = {0ull, 0ull, 0ull, 0ull};
    int buf = 0;
    for (int k0 = 0; k0 < Hn; k0 += 16) {
        if (aAct) {
            sA[buf][ak+0][ar]=ra.x; sA[buf][ak+1][ar]=ra.y;
            sA[buf][ak+2][ar]=ra.z; sA[buf][ak+3][ar]=ra.w;
        }
        sW[buf][wk+0][wn]=rw.x; sW[buf][wk+1][wn]=rw.y;
        sW[buf][wk+2][wn]=rw.z; sW[buf][wk+3][wn]=rw.w;
        __syncthreads();
        if (k0 + 16 < Hn) {
            if (aAct) ra = *(const float4*)(Ap + k0 + 16);
            rw = *(const float4*)(Wp + k0 + 16);
        }
        #pragma unroll
        for (int kk = 0; kk < 16; kk++) {
            const float a = sA[buf][kk][lane];
            const u64t ap = pk2(a, a);
            const ulonglong2 w0 = *(const ulonglong2*)&sW[buf][kk][w8];
            const ulonglong2 w1 = *(const ulonglong2*)&sW[buf][kk][w8 + 4];
            acc[0] = ffma2(ap, w0.x, acc[0]);
            acc[1] = ffma2(ap, w0.y, acc[1]);
            acc[2] = ffma2(ap, w1.x, acc[2]);
            acc[3] = ffma2(ap, w1.y, acc[3]);
        }
        buf ^= 1;
    }
    // transpose via smem for coalesced stores
    float r[8];
    upk2(acc[0], r[0], r[1]); upk2(acc[1], r[2], r[3]);
    upk2(acc[2], r[4], r[5]); upk2(acc[3], r[6], r[7]);
    __syncthreads();
    *(float4*)&stg[lane*68 + w8]     = make_float4(r[0], r[1], r[2], r[3]);
    *(float4*)&stg[lane*68 + w8 + 4] = make_float4(r[4], r[5], r[6], r[7]);
    __syncthreads();
    const int row = tid >> 3;             // 0..31
    const int col = (tid & 7) << 3;       // 0..56
    float4 v0 = *(const float4*)&stg[row*68 + col];
    float4 v1 = *(const float4*)&stg[row*68 + col + 4];
    const float4 b0 = *(const float4*)(bias + n0 + col);
    const float4 b1 = *(const float4*)(bias + n0 + col + 4);
    float* Cr = C + (size_t)(m0 + row) * Hn + n0 + col;
    *(float4*)Cr       = make_float4(v0.x+b0.x, v0.y+b0.y, v0.z+b0.z, v0.w+b0.w);
    *(float4*)(Cr + 4) = make_float4(v1.x+b1.x, v1.y+b1.y, v1.z+b1.z, v1.w+b1.w);
}

// ---------------- one-time setup ----------------
__global__ void setup_kernel(
    const float* __restrict__ dec, const float* __restrict__ h0,
    const float* __restrict__ c0, const float* __restrict__ courier,
    const unsigned char* __restrict__ im,
    const float* __restrict__ W_ih, const float* __restrict__ W_hh,
    const float* __restrict__ b_ih, const float* __restrict__ b_hh)
{
    int i = blockIdx.x * blockDim.x + threadIdx.x;
    if (i == 0) g_sync = 0;
    if (i < G4*KX) {
        int n = i / KX, k = i % KX;
        g_Wcat[i] = (k < En) ? W_ih[n*En + k] : W_hh[n*Hn + (k - En)];
    }
    if (i < G4)    g_bcat[i] = b_ih[i] + b_hh[i];
    if (i < Bn*KX) {
        int b = i / KX, j = i % KX;
        g_xh[i] = (j < En) ? dec[b*En + j] : h0[b*Hn + (j - En)];
    }
    if (i < Bn*Hn) g_c[i] = c0[i];
    if (i < Bn*CD) {
        int b = i / CD, j = i % CD;
        g_hc[b*HCn + Hn + j] = courier[i];
    }
    if (i < Bn*Ln) g_mask[i] = im[i];
}

// ---------------- the persistent decoder kernel -----------------------------
__global__ __launch_bounds__(256, 2) void persist_kernel(
    const float* __restrict__ emb,
    const float* __restrict__ Wm,   const float* __restrict__ bm,
    const float* __restrict__ Wq_g, const float* __restrict__ bq_g,
    const float* __restrict__ Wq_p, const float* __restrict__ bq_p,
    const float* __restrict__ v_g,  const float* __restrict__ v_p,
    float* __restrict__ out)
{
    extern __shared__ float es[];                // 64 KB e-tile
    __shared__ float sA[2][16][32];
    __shared__ float sW[2][16][64];
    __shared__ float qs[256], vs[256], wv[64];
    __shared__ float s_m, s_ls;
    __shared__ int   s_sel;

    const int t = threadIdx.x;
    const int warp = t >> 5, lane = t & 31;
    const int nthr = gridDim.x * blockDim.x;
    unsigned int barcnt = 0;

    for (int step = 0; step < Ln; step++) {
        // ---- P1: gates = [x|h] @ Wcat^T + bcat ----
        gemm_gates(g_xh, g_Wcat, g_bcat, g_gates, sA, sW);
        gbar(barcnt);

        // ---- P2: LSTM pointwise ----
        for (int i = blockIdx.x * blockDim.x + t; i < Bn*Hn; i += nthr) {
            int b = i >> 8, j = i & 255;
            const float* g = g_gates + b*G4;
            float iv = sigf(g[j]);
            float fv = sigf(g[j + 256]);
            float gv = tanhf(g[j + 512]);
            float ov = sigf(g[j + 768]);
            float c = fv * g_c[i] + iv * gv;
            float h = ov * tanhf(c);
            g_c[i]              = c;
            g_xh[b*KX + En + j] = h;
            g_hc[b*HCn + j]     = h;
        }
        gbar(barcnt);

        // ---- P3: gl = [h|courier] @ Wm^T + bm  (K=320) ----
        gemm_phase<16>(g_hc, Wm, bm, g_gl, Bn, Hn, HCn, sA, sW);
        gbar(barcnt);

        // ---- P4: qg = gl @ Wq_g^T + bq_g ----
        gemm_phase<16>(g_gl, Wq_g, bq_g, g_qg, Bn, Hn, Hn, sA, sW);
        gbar(barcnt);

        // ---- P5: attention g (scores + softmax + weighted sum) ----
        for (int b = blockIdx.x; b < Bn; b += gridDim.x) {
            __syncthreads();
            const float4* src = (const float4*)(g_eg + (size_t)b * Ln * Hn);
            float4* d4 = (float4*)es;
            #pragma unroll
            for (int i = t; i < 4096; i += 256) d4[i] = src[i];
            qs[t] = g_qg[b*Hn + t];
            vs[t] = v_g[t];
            __syncthreads();

            #pragma unroll
            for (int l0 = 0; l0 < 64; l0 += 8) {
                int l = l0 + warp;
                const float* row = es + l * 256;
                float acc = 0.f;
                #pragma unroll
                for (int j = 0; j < 8; j++) {
                    int h = lane + 32*j;
                    acc += vs[h] * tanh_pade(qs[h] + row[h]);
                }
                #pragma unroll
                for (int o = 16; o; o >>= 1) acc += __shfl_xor_sync(0xffffffffu, acc, o);
                if (lane == 0) wv[l] = g_mask[b*Ln + l] ? NEGV : acc;
            }
            __syncthreads();

            if (warp == 0) {
                float a = wv[lane], c = wv[lane + 32];
                float m = fmaxf(a, c);
                #pragma unroll
                for (int o = 16; o; o >>= 1) m = fmaxf(m, __shfl_xor_sync(0xffffffffu, m, o));
                float ea = expf(a - m), ec = expf(c - m);
                float s = ea + ec;
                #pragma unroll
                for (int o = 16; o; o >>= 1) s += __shfl_xor_sync(0xffffffffu, s, o);
                wv[lane]      = ea / s;
                wv[lane + 32] = ec / s;
            }
            __syncthreads();

            float acc = 0.f;
            #pragma unroll
            for (int l = 0; l < 64; l++) acc += es[l*256 + t] * wv[l];
            g_gl2[b*Hn + t] = acc;
        }
        gbar(barcnt);

        // ---- P6: qp = gl2 @ Wq_p^T + bq_p ----
        gemm_phase<16>(g_gl2, Wq_p, bq_p, g_qp, Bn, Hn, Hn, sA, sW);
        gbar(barcnt);

        // ---- P7: attention p (log-softmax + argmax + mask + gather) ----
        for (int b = blockIdx.x; b < Bn; b += gridDim.x) {
            __syncthreads();
            const float4* src = (const float4*)(g_ep + (size_t)b * Ln * Hn);
            float4* d4 = (float4*)es;
            #pragma unroll
            for (int i = t; i < 4096; i += 256) d4[i] = src[i];
            qs[t] = g_qp[b*Hn + t];
            vs[t] = v_p[t];
            __syncthreads();

            #pragma unroll
            for (int l0 = 0; l0 < 64; l0 += 8) {
                int l = l0 + warp;
                const float* row = es + l * 256;
                float acc = 0.f;
                #pragma unroll
                for (int j = 0; j < 8; j++) {
                    int h = lane + 32*j;
                    acc += vs[h] * tanh_pade(qs[h] + row[h]);
                }
                #pragma unroll
                for (int o = 16; o; o >>= 1) acc += __shfl_xor_sync(0xffffffffu, acc, o);
                if (lane == 0) wv[l] = g_mask[b*Ln + l] ? NEGV : (10.0f * tanhf(acc));
            }
            __syncthreads();

            if (warp == 0) {
                float a = wv[lane], c = wv[lane + 32];
                float m = fmaxf(a, c);
                #pragma unroll
                for (int o = 16; o; o >>= 1) m = fmaxf(m, __shfl_xor_sync(0xffffffffu, m, o));
                float s = expf(a - m) + expf(c - m);
                #pragma unroll
                for (int o = 16; o; o >>= 1) s += __shfl_xor_sync(0xffffffffu, s, o);
                float bv = a; int bi = lane;
                if (c > bv) { bv = c; bi = lane + 32; }
                #pragma unroll
                for (int o = 16; o; o >>= 1) {
                    float ov = __shfl_xor_sync(0xffffffffu, bv, o);
                    int   oi = __shfl_xor_sync(0xffffffffu, bi, o);
                    if (ov > bv || (ov == bv && oi < bi)) { bv = ov; bi = oi; }
                }
                if (lane == 0) {
                    s_m = m; s_ls = logf(s); s_sel = bi;
                    unsigned char* mk = g_mask + b*Ln;
                    mk[bi] = 1;
                    int cnt = 0;
                    #pragma unroll
                    for (int l = 0; l < Ln; l++) cnt += mk[l];
                    if (cnt == Ln) mk[Ln - 1] = 0;
                    out[(size_t)(Bn*Ln*Ln) + (size_t)b*Ln + step] = (float)bi;
                }
            }
            __syncthreads();

            if (t < Ln)
                out[(size_t)b*Ln*Ln + (size_t)step*Ln + t] = wv[t] - s_m - s_ls;

            int sel = s_sel;
            g_xh[b*KX + t] = emb[((size_t)sel*Bn + b)*En + t];
        }
        gbar(barcnt);
    }
}

// ---------------- host ----------------
extern "C" void kernel_launch(void* const* d_in, const int* in_sizes, int n_in,
                              void* d_out, int out_size)
{
    const float* dec     = (const float*)d_in[0];
    const float* emb     = (const float*)d_in[1];
    const float* h0      = (const float*)d_in[2];
    const float* c0      = (const float*)d_in[3];
    const float* ctx     = (const float*)d_in[4];
    const float* courier = (const float*)d_in[5];
    const unsigned char* initm = (const unsigned char*)d_in[6];
    const float* W_ih = (const float*)d_in[7];
    const float* W_hh = (const float*)d_in[8];
    const float* b_ih = (const float*)d_in[9];
    const float* b_hh = (const float*)d_in[10];
    const float* Wm   = (const float*)d_in[11];
    const float* bm   = (const float*)d_in[12];
    const float* Wq_p = (const float*)d_in[13];
    const float* bq_p = (const float*)d_in[14];
    const float* Wr_p = (const float*)d_in[15];
    const float* br_p = (const float*)d_in[16];
    const float* v_p  = (const float*)d_in[17];
    const float* Wq_g = (const float*)d_in[18];
    const float* bq_g = (const float*)d_in[19];
    const float* Wr_g = (const float*)d_in[20];
    const float* br_g = (const float*)d_in[21];
    const float* v_g  = (const float*)d_in[22];
    float* out = (float*)d_out;

    cudaFuncSetAttribute(persist_kernel, cudaFuncAttributeMaxDynamicSharedMemorySize, 65536);

    float *eg, *ep;
    cudaGetSymbolAddress((void**)&eg, g_eg);
    cudaGetSymbolAddress((void**)&ep, g_ep);

    setup_kernel<<<1024, 512>>>(dec, h0, c0, courier, initm, W_ih, W_hh, b_ih, b_hh);

    // e_g / e_p = context @ Wr^T + br, stored [b][l][h]
    gemm_e_bcast<<<4096, 256>>>(ctx, Wr_g, br_g, eg);
    gemm_e_bcast<<<4096, 256>>>(ctx, Wr_p, br_p, ep);

    persist_kernel<<<NBLK, 256, 65536>>>(emb, Wm, bm, Wq_g, bq_g, Wq_p, bq_p,
                                         v_g, v_p, out);
}